// round 7
// baseline (speedup 1.0000x reference)
#include <cuda_runtime.h>
#include <cuda_fp16.h>
#include <cstdint>

// ExpertScatter: out[b, Ind[b,h,k], :] += Y[b,h,k,:] @ W[h]
// R7: fp16 mma, 1024-thread CTA (32 warps, <=64 regs), pre-converted fp16
//     inputs in __device__ scratch, cp.async staging, REDG.v2 epilogue.

#define BB 8
#define HH 16
#define KDIM 1024
#define DD 128
#define NN 1024
#define TT 4096

#define TM 256
#define TN 128
#define NCHUNK 8
#define THREADS 1024

#define AS_BYTES (TM * DD * 2)                   // 65536
#define BS_BYTES (DD * TN * 2)                   // 32768
#define SMEM_BYTES (AS_BYTES + 2 * BS_BYTES)     // 131072

__device__ __align__(16) __half g_Yh[BB * HH * KDIM * DD];   // 67 MB scratch
__device__ __align__(16) __half g_Wh[HH * DD * NN];          // 4 MB scratch

__global__ void zero_out_kernel(float4* __restrict__ p, int n4) {
    int i = blockIdx.x * blockDim.x + threadIdx.x;
    if (i < n4) p[i] = make_float4(0.f, 0.f, 0.f, 0.f);
}

__device__ __forceinline__ uint32_t pack_h2(float a, float b) {
    __half2 h = __floats2half2_rn(a, b);
    return *(uint32_t*)&h;
}

__global__ void convert_kernel(const float* __restrict__ src, __half* __restrict__ dst, int n8) {
    int i = blockIdx.x * blockDim.x + threadIdx.x;
    if (i >= n8) return;
    const float4 v0 = ((const float4*)src)[2 * i];
    const float4 v1 = ((const float4*)src)[2 * i + 1];
    uint4 w = { pack_h2(v0.x, v0.y), pack_h2(v0.z, v0.w),
                pack_h2(v1.x, v1.y), pack_h2(v1.z, v1.w) };
    ((uint4*)dst)[i] = w;
}

__device__ __forceinline__ uint32_t smem_u32(const void* p) {
    uint32_t a;
    asm("{ .reg .u64 t; cvta.to.shared.u64 t, %1; cvt.u32.u64 %0, t; }" : "=r"(a) : "l"(p));
    return a;
}
__device__ __forceinline__ void cp16(uint32_t dst, const void* src) {
    asm volatile("cp.async.cg.shared.global [%0], [%1], 16;" :: "r"(dst), "l"(src));
}
#define CP_COMMIT() asm volatile("cp.async.commit_group;" ::: "memory")
#define CP_WAIT0()  asm volatile("cp.async.wait_group 0;" ::: "memory")

__device__ __forceinline__ void ldsm_x4(uint32_t* r, uint32_t addr) {
    asm volatile("ldmatrix.sync.aligned.m8n8.x4.shared.b16 {%0,%1,%2,%3}, [%4];"
                 : "=r"(r[0]), "=r"(r[1]), "=r"(r[2]), "=r"(r[3]) : "r"(addr));
}
__device__ __forceinline__ void ldsm_x4_t(uint32_t* r, uint32_t addr) {
    asm volatile("ldmatrix.sync.aligned.m8n8.x4.trans.shared.b16 {%0,%1,%2,%3}, [%4];"
                 : "=r"(r[0]), "=r"(r[1]), "=r"(r[2]), "=r"(r[3]) : "r"(addr));
}
__device__ __forceinline__ void mma_f16(float* c, const uint32_t* a, const uint32_t* b) {
    asm volatile(
        "mma.sync.aligned.m16n8k16.row.col.f32.f16.f16.f32 "
        "{%0,%1,%2,%3}, {%4,%5,%6,%7}, {%8,%9}, {%0,%1,%2,%3};"
        : "+f"(c[0]), "+f"(c[1]), "+f"(c[2]), "+f"(c[3])
        : "r"(a[0]), "r"(a[1]), "r"(a[2]), "r"(a[3]), "r"(b[0]), "r"(b[1]));
}
__device__ __forceinline__ void red_v2(float* p, float x, float y) {
    asm volatile("red.global.add.v2.f32 [%0], {%1, %2};"
                 :: "l"(p), "f"(x), "f"(y) : "memory");
}

__global__ void __launch_bounds__(THREADS, 1)
expert_scatter_f16(const int* __restrict__ Ind, float* __restrict__ out) {
    const int b  = blockIdx.z;
    const int h  = blockIdx.y;
    const int k0 = blockIdx.x * TM;

    extern __shared__ char sm[];
    char* As = sm;
    const uint32_t As_a = smem_u32(As);
    const uint32_t Bs_a[2] = { As_a + AS_BYTES, As_a + AS_BYTES + BS_BYTES };
    __shared__ int sInd[TM];

    const int tid  = threadIdx.x;
    const int warp = tid >> 5;
    const int lane = tid & 31;
    const int g    = lane >> 2;
    const int tig  = lane & 3;
    const int wm   = warp >> 2;   // 0..7 : 32-row band
    const int wn   = warp & 3;    // 0..3 : 32-col band

    // ---- Prologue: cp.async A tile + B chunk 0 ----
    const __half* Ysrc = g_Yh + ((size_t)(b * HH + h) * KDIM + k0) * DD;
    #pragma unroll
    for (int i = 0; i < 4; i++) {
        const int flat = i * THREADS + tid;
        const int m = flat >> 4;
        const int c = flat & 15;
        cp16(As_a + m * 256 + ((c ^ (m & 7)) << 4), Ysrc + (size_t)m * DD + c * 8);
    }
    const __half* Wsrc = g_Wh + (size_t)h * DD * NN;
    #pragma unroll
    for (int i = 0; i < 2; i++) {
        const int flat = i * THREADS + tid;
        const int k = flat >> 4;
        const int c = flat & 15;
        cp16(Bs_a[0] + k * 256 + ((c ^ (k & 7)) << 4), Wsrc + (size_t)k * NN + c * 8);
    }
    CP_COMMIT();
    if (tid < TM) sInd[tid] = Ind[(size_t)(b * HH + h) * KDIM + k0 + tid];
    CP_WAIT0();
    __syncthreads();

    float* outb = out + (size_t)b * TT * NN;

    // ldmatrix lane-address components
    const int a_ml_base = wm * 32 + ((lane >> 3) & 1) * 8 + (lane & 7);
    const int a_chi     = lane >> 4;
    const int b_kl_base = ((lane >> 3) & 1) * 8 + (lane & 7);

    #pragma unroll 1
    for (int nc = 0; nc < NCHUNK; nc++) {
        const int buf = nc & 1;

        // ---- Issue cp.async for next B chunk into other buffer ----
        if (nc + 1 < NCHUNK) {
            const __half* Wn = Wsrc + (size_t)(nc + 1) * TN;
            #pragma unroll
            for (int i = 0; i < 2; i++) {
                const int flat = i * THREADS + tid;
                const int k = flat >> 4;
                const int c = flat & 15;
                cp16(Bs_a[buf ^ 1] + k * 256 + ((c ^ (k & 7)) << 4),
                     Wn + (size_t)k * NN + c * 8);
            }
        }
        CP_COMMIT();

        // ---- Compute: warp tile 32m x 32n = 2(im) x 4(in) x 8(kt) ----
        float acc[2][4][4];
        #pragma unroll
        for (int im = 0; im < 2; im++)
            #pragma unroll
            for (int in = 0; in < 4; in++)
                #pragma unroll
                for (int c = 0; c < 4; c++) acc[im][in][c] = 0.f;

        #pragma unroll
        for (int kt = 0; kt < 8; kt++) {
            uint32_t a[2][4], bfr[2][4];
            #pragma unroll
            for (int im = 0; im < 2; im++) {
                const int ml = a_ml_base + im * 16;
                const int c  = kt * 2 + a_chi;
                ldsm_x4(a[im], As_a + ml * 256 + ((c ^ (ml & 7)) << 4));
            }
            #pragma unroll
            for (int inp = 0; inp < 2; inp++) {
                const int kl = kt * 16 + b_kl_base;
                const int c  = wn * 4 + inp * 2 + (lane >> 4);
                ldsm_x4_t(bfr[inp], Bs_a[buf] + kl * 256 + ((c ^ (kl & 7)) << 4));
            }
            #pragma unroll
            for (int in = 0; in < 4; in++) {
                const uint32_t bb[2] = { bfr[in >> 1][(in & 1) * 2],
                                         bfr[in >> 1][(in & 1) * 2 + 1] };
                #pragma unroll
                for (int im = 0; im < 2; im++)
                    mma_f16(acc[im][in], a[im], bb);
            }
        }

        // ---- Epilogue: vectorized scatter-add (indices from smem) ----
        const int colb = nc * TN + wn * 32 + tig * 2;
        #pragma unroll
        for (int im = 0; im < 2; im++) {
            const int mrow = wm * 32 + im * 16;
            const int t0 = sInd[mrow + g];
            const int t1 = sInd[mrow + g + 8];
            float* r0 = outb + (size_t)t0 * NN + colb;
            float* r1 = outb + (size_t)t1 * NN + colb;
            #pragma unroll
            for (int in = 0; in < 4; in++) {
                red_v2(r0 + in * 8, acc[im][in][0], acc[im][in][1]);
                red_v2(r1 + in * 8, acc[im][in][2], acc[im][in][3]);
            }
        }

        CP_WAIT0();
        __syncthreads();
    }
}

extern "C" void kernel_launch(void* const* d_in, const int* in_sizes, int n_in,
                              void* d_out, int out_size) {
    const float* Y   = (const float*)d_in[0];
    const int*   Ind = (const int*)d_in[1];
    const float* W   = (const float*)d_in[n_in - 1];
    float* out = (float*)d_out;

    void *yh_p = nullptr, *wh_p = nullptr;
    cudaGetSymbolAddress(&yh_p, g_Yh);
    cudaGetSymbolAddress(&wh_p, g_Wh);

    // zero output (poisoned 0xAA)
    const int n4 = (BB * TT * NN) / 4;
    zero_out_kernel<<<(n4 + 511) / 512, 512>>>((float4*)out, n4);

    // pre-convert Y and W to fp16 scratch
    const int ny8 = (BB * HH * KDIM * DD) / 8;
    convert_kernel<<<(ny8 + 511) / 512, 512>>>(Y, (__half*)yh_p, ny8);
    const int nw8 = (HH * DD * NN) / 8;
    convert_kernel<<<(nw8 + 511) / 512, 512>>>(W, (__half*)wh_p, nw8);

    cudaFuncSetAttribute(expert_scatter_f16,
                         cudaFuncAttributeMaxDynamicSharedMemorySize, SMEM_BYTES);
    dim3 grid(KDIM / TM, HH, BB);   // 4 x 16 x 8 = 512 CTAs
    expert_scatter_f16<<<grid, THREADS, SMEM_BYTES>>>(Ind, out);
}

// round 8
// speedup vs baseline: 1.0907x; 1.0907x over previous
#include <cuda_runtime.h>
#include <cuda_fp16.h>
#include <cstdint>

// ExpertScatter: out[b, Ind[b,h,k], :] += Y[b,h,k,:] @ W[h]
// R8: fp16 mma (R6 base), shfl pair-exchange + red.global.add.v4 epilogue,
//     prefetch-before-compute, single barrier per chunk.

#define BB 8
#define HH 16
#define KDIM 1024
#define DD 128
#define NN 1024
#define TT 4096

#define TM 256
#define TN 128
#define NCHUNK 8
#define THREADS 512

#define AS_BYTES (TM * DD * 2)          // 65536
#define BS_BYTES (DD * TN * 2)          // 32768
#define SMEM_BYTES (AS_BYTES + 2 * BS_BYTES)   // 131072

__global__ void zero_out_kernel(float4* __restrict__ p, int n4) {
    int i = blockIdx.x * blockDim.x + threadIdx.x;
    if (i < n4) p[i] = make_float4(0.f, 0.f, 0.f, 0.f);
}

__device__ __forceinline__ uint32_t smem_u32(const void* p) {
    uint32_t a;
    asm("{ .reg .u64 t; cvta.to.shared.u64 t, %1; cvt.u32.u64 %0, t; }" : "=r"(a) : "l"(p));
    return a;
}
__device__ __forceinline__ uint32_t pack_h2(float a, float b) {
    __half2 h = __floats2half2_rn(a, b);
    return *(uint32_t*)&h;
}
__device__ __forceinline__ void ldsm_x4(uint32_t* r, uint32_t addr) {
    asm volatile("ldmatrix.sync.aligned.m8n8.x4.shared.b16 {%0,%1,%2,%3}, [%4];"
                 : "=r"(r[0]), "=r"(r[1]), "=r"(r[2]), "=r"(r[3]) : "r"(addr));
}
__device__ __forceinline__ void ldsm_x4_t(uint32_t* r, uint32_t addr) {
    asm volatile("ldmatrix.sync.aligned.m8n8.x4.trans.shared.b16 {%0,%1,%2,%3}, [%4];"
                 : "=r"(r[0]), "=r"(r[1]), "=r"(r[2]), "=r"(r[3]) : "r"(addr));
}
__device__ __forceinline__ void mma_f16(float* c, const uint32_t* a, const uint32_t* b) {
    asm volatile(
        "mma.sync.aligned.m16n8k16.row.col.f32.f16.f16.f32 "
        "{%0,%1,%2,%3}, {%4,%5,%6,%7}, {%8,%9}, {%0,%1,%2,%3};"
        : "+f"(c[0]), "+f"(c[1]), "+f"(c[2]), "+f"(c[3])
        : "r"(a[0]), "r"(a[1]), "r"(a[2]), "r"(a[3]), "r"(b[0]), "r"(b[1]));
}
__device__ __forceinline__ void red_v4(float* p, float x, float y, float z, float w) {
    asm volatile("red.global.add.v4.f32 [%0], {%1, %2, %3, %4};"
                 :: "l"(p), "f"(x), "f"(y), "f"(z), "f"(w) : "memory");
}

__global__ void __launch_bounds__(THREADS, 1)
expert_scatter_f16(const float* __restrict__ Y,
                   const int*   __restrict__ Ind,
                   const float* __restrict__ W,
                   float*       __restrict__ out) {
    const int b  = blockIdx.z;
    const int h  = blockIdx.y;
    const int k0 = blockIdx.x * TM;

    extern __shared__ char sm[];
    char* As = sm;
    char* Bs[2] = { sm + AS_BYTES, sm + AS_BYTES + BS_BYTES };
    __shared__ int sInd[TM];

    const int tid  = threadIdx.x;
    const int warp = tid >> 5;
    const int lane = tid & 31;
    const int g    = lane >> 2;
    const int tig  = lane & 3;
    const int pa   = tig & 1;        // pair parity
    const int aa   = tig >> 1;       // pair index (0/1)
    const int wm   = warp >> 2;      // 0..3 : 64-row band
    const int wn   = warp & 3;       // 0..3 : 32-col band

    const uint32_t As_a = smem_u32(As);
    const uint32_t Bs_a[2] = { smem_u32(Bs[0]), smem_u32(Bs[1]) };

    // ---- Stage A: Y[256m x 128k] f32 -> fp16 [m][k], 16B chunks, c ^= m&7 ----
    const float* Yp = Y + ((size_t)(b * HH + h) * KDIM + k0) * DD;
    #pragma unroll
    for (int i = 0; i < 8; i++) {
        const int flat = i * THREADS + tid;
        const int m = flat >> 4;
        const int c = flat & 15;
        const float4 v0 = *(const float4*)(Yp + (size_t)m * DD + c * 8);
        const float4 v1 = *(const float4*)(Yp + (size_t)m * DD + c * 8 + 4);
        uint4 w = { pack_h2(v0.x, v0.y), pack_h2(v0.z, v0.w),
                    pack_h2(v1.x, v1.y), pack_h2(v1.z, v1.w) };
        *(uint4*)(As + m * 256 + ((c ^ (m & 7)) << 4)) = w;
    }
    if (tid < TM) sInd[tid] = Ind[(size_t)(b * HH + h) * KDIM + k0 + tid];

    const float* Wh = W + (size_t)h * DD * NN;
    float* outb = out + (size_t)b * TT * NN;

    // ---- Stage B chunk 0 ----
    #pragma unroll
    for (int i = 0; i < 4; i++) {
        const int flat = i * THREADS + tid;
        const int k = flat >> 4;
        const int c = flat & 15;
        const float4 v0 = *(const float4*)(Wh + (size_t)k * NN + c * 8);
        const float4 v1 = *(const float4*)(Wh + (size_t)k * NN + c * 8 + 4);
        uint4 w = { pack_h2(v0.x, v0.y), pack_h2(v0.z, v0.w),
                    pack_h2(v1.x, v1.y), pack_h2(v1.z, v1.w) };
        *(uint4*)(Bs[0] + k * 256 + ((c ^ (k & 7)) << 4)) = w;
    }
    __syncthreads();

    // per-warp scatter rows
    int t0s[4], t1s[4];
    #pragma unroll
    for (int im = 0; im < 4; im++) {
        const int mrow = wm * 64 + im * 16;
        t0s[im] = sInd[mrow + g];
        t1s[im] = sInd[mrow + g + 8];
    }

    const int a_ml_base = wm * 64 + ((lane >> 3) & 1) * 8 + (lane & 7);
    const int a_chi     = lane >> 4;
    const int b_kl_base = ((lane >> 3) & 1) * 8 + (lane & 7);

    #pragma unroll 1
    for (int nc = 0; nc < NCHUNK; nc++) {
        const int buf = nc & 1;
        const bool has_next = (nc + 1 < NCHUNK);

        // ---- Prefetch+pack next B chunk BEFORE compute (latency hidden) ----
        uint4 pf[4];
        if (has_next) {
            const float* Wn = Wh + (size_t)(nc + 1) * TN;
            #pragma unroll
            for (int i = 0; i < 4; i++) {
                const int flat = i * THREADS + tid;
                const int k = flat >> 4;
                const int c = flat & 15;
                const float4 v0 = *(const float4*)(Wn + (size_t)k * NN + c * 8);
                const float4 v1 = *(const float4*)(Wn + (size_t)k * NN + c * 8 + 4);
                pf[i].x = pack_h2(v0.x, v0.y); pf[i].y = pack_h2(v0.z, v0.w);
                pf[i].z = pack_h2(v1.x, v1.y); pf[i].w = pack_h2(v1.z, v1.w);
            }
        }

        // ---- Compute: warp tile 64m x 32n = 4(im) x 4(in) x 8(kt) ----
        float acc[4][4][4];
        #pragma unroll
        for (int im = 0; im < 4; im++)
            #pragma unroll
            for (int in = 0; in < 4; in++)
                #pragma unroll
                for (int c = 0; c < 4; c++) acc[im][in][c] = 0.f;

        #pragma unroll
        for (int kt = 0; kt < 8; kt++) {
            uint32_t a[4][4], bfr[2][4];
            #pragma unroll
            for (int im = 0; im < 4; im++) {
                const int ml = a_ml_base + im * 16;
                const int c  = kt * 2 + a_chi;
                ldsm_x4(a[im], As_a + ml * 256 + ((c ^ (ml & 7)) << 4));
            }
            #pragma unroll
            for (int inp = 0; inp < 2; inp++) {
                const int kl = kt * 16 + b_kl_base;
                const int c  = wn * 4 + inp * 2 + (lane >> 4);
                ldsm_x4_t(bfr[inp], Bs_a[buf] + kl * 256 + ((c ^ (kl & 7)) << 4));
            }
            #pragma unroll
            for (int in = 0; in < 4; in++) {
                const uint32_t bb[2] = { bfr[in >> 1][(in & 1) * 2],
                                         bfr[in >> 1][(in & 1) * 2 + 1] };
                #pragma unroll
                for (int im = 0; im < 4; im++)
                    mma_f16(acc[im][in], a[im], bb);
            }
        }

        // ---- Commit prefetched B into the other buffer ----
        if (has_next) {
            #pragma unroll
            for (int i = 0; i < 4; i++) {
                const int flat = i * THREADS + tid;
                const int k = flat >> 4;
                const int c = flat & 15;
                *(uint4*)(Bs[buf ^ 1] + k * 256 + ((c ^ (k & 7)) << 4)) = pf[i];
            }
        }

        // ---- Epilogue: pair-exchange -> row-contiguous red.v4 ----
        // even-parity lane (pa=0): quads for in 0,1 ; odd: in 2,3
        const int colq = nc * TN + wn * 32 + aa * 4;
        #pragma unroll
        for (int im = 0; im < 4; im++) {
            #pragma unroll
            for (int hf = 0; hf < 2; hf++) {
                const int c0 = hf * 2;
                const float s0 = pa ? acc[im][0][c0]     : acc[im][2][c0];
                const float s1 = pa ? acc[im][0][c0 + 1] : acc[im][2][c0 + 1];
                const float s2 = pa ? acc[im][1][c0]     : acc[im][3][c0];
                const float s3 = pa ? acc[im][1][c0 + 1] : acc[im][3][c0 + 1];
                const float x0 = __shfl_xor_sync(0xffffffffu, s0, 1);
                const float x1 = __shfl_xor_sync(0xffffffffu, s1, 1);
                const float x2 = __shfl_xor_sync(0xffffffffu, s2, 1);
                const float x3 = __shfl_xor_sync(0xffffffffu, s3, 1);
                const int t = hf ? t1s[im] : t0s[im];
                float* rp = outb + (size_t)t * NN + colq;
                if (pa == 0) {
                    red_v4(rp,      acc[im][0][c0], acc[im][0][c0 + 1], x0, x1);
                    red_v4(rp + 8,  acc[im][1][c0], acc[im][1][c0 + 1], x2, x3);
                } else {
                    red_v4(rp + 16, x0, x1, acc[im][2][c0], acc[im][2][c0 + 1]);
                    red_v4(rp + 24, x2, x3, acc[im][3][c0], acc[im][3][c0 + 1]);
                }
            }
        }

        if (has_next) __syncthreads();   // STS(buf^1) visible before next compute
    }
}

extern "C" void kernel_launch(void* const* d_in, const int* in_sizes, int n_in,
                              void* d_out, int out_size) {
    const float* Y   = (const float*)d_in[0];
    const int*   Ind = (const int*)d_in[1];
    const float* W   = (const float*)d_in[n_in - 1];
    float* out = (float*)d_out;

    const int n4 = (BB * TT * NN) / 4;
    zero_out_kernel<<<(n4 + 511) / 512, 512>>>((float4*)out, n4);

    cudaFuncSetAttribute(expert_scatter_f16,
                         cudaFuncAttributeMaxDynamicSharedMemorySize, SMEM_BYTES);
    dim3 grid(KDIM / TM, HH, BB);   // 4 x 16 x 8 = 512 CTAs
    expert_scatter_f16<<<grid, THREADS, SMEM_BYTES>>>(Y, Ind, W, out);
}

// round 9
// speedup vs baseline: 1.4460x; 1.3258x over previous
#include <cuda_runtime.h>
#include <cuda_fp16.h>
#include <cstdint>

// ExpertScatter: out[b, Ind[b,h,k], :] += Y[b,h,k,:] @ W[h]
// R9: fp16 mma, TM=128 / 256-thread CTAs, 2 CTAs/SM (overlapping pipelines),
//     W pre-converted to fp16 scratch + cp.async B staging, red.v2 epilogue.

#define BB 8
#define HH 16
#define KDIM 1024
#define DD 128
#define NN 1024
#define TT 4096

#define TM 128
#define TN 128
#define NCHUNK 8
#define THREADS 256

#define AS_BYTES (TM * DD * 2)                 // 32768
#define BS_BYTES (DD * TN * 2)                 // 32768
#define SMEM_BYTES (AS_BYTES + 2 * BS_BYTES)   // 98304  (2 CTAs = 192KB <= 227KB)

__device__ __align__(16) __half g_Wh[HH * DD * NN];   // 4 MB fp16 W scratch

__global__ void zero_out_kernel(float4* __restrict__ p, int n4) {
    int i = blockIdx.x * blockDim.x + threadIdx.x;
    if (i < n4) p[i] = make_float4(0.f, 0.f, 0.f, 0.f);
}

__device__ __forceinline__ uint32_t pack_h2(float a, float b) {
    __half2 h = __floats2half2_rn(a, b);
    return *(uint32_t*)&h;
}

__global__ void convert_w_kernel(const float* __restrict__ src, __half* __restrict__ dst, int n8) {
    int i = blockIdx.x * blockDim.x + threadIdx.x;
    if (i >= n8) return;
    const float4 v0 = ((const float4*)src)[2 * i];
    const float4 v1 = ((const float4*)src)[2 * i + 1];
    uint4 w = { pack_h2(v0.x, v0.y), pack_h2(v0.z, v0.w),
                pack_h2(v1.x, v1.y), pack_h2(v1.z, v1.w) };
    ((uint4*)dst)[i] = w;
}

__device__ __forceinline__ uint32_t smem_u32(const void* p) {
    uint32_t a;
    asm("{ .reg .u64 t; cvta.to.shared.u64 t, %1; cvt.u32.u64 %0, t; }" : "=r"(a) : "l"(p));
    return a;
}
__device__ __forceinline__ void cp16(uint32_t dst, const void* src) {
    asm volatile("cp.async.cg.shared.global [%0], [%1], 16;" :: "r"(dst), "l"(src));
}
#define CP_COMMIT() asm volatile("cp.async.commit_group;" ::: "memory")
#define CP_WAIT0()  asm volatile("cp.async.wait_group 0;" ::: "memory")

__device__ __forceinline__ void ldsm_x4(uint32_t* r, uint32_t addr) {
    asm volatile("ldmatrix.sync.aligned.m8n8.x4.shared.b16 {%0,%1,%2,%3}, [%4];"
                 : "=r"(r[0]), "=r"(r[1]), "=r"(r[2]), "=r"(r[3]) : "r"(addr));
}
__device__ __forceinline__ void ldsm_x4_t(uint32_t* r, uint32_t addr) {
    asm volatile("ldmatrix.sync.aligned.m8n8.x4.trans.shared.b16 {%0,%1,%2,%3}, [%4];"
                 : "=r"(r[0]), "=r"(r[1]), "=r"(r[2]), "=r"(r[3]) : "r"(addr));
}
__device__ __forceinline__ void mma_f16(float* c, const uint32_t* a, const uint32_t* b) {
    asm volatile(
        "mma.sync.aligned.m16n8k16.row.col.f32.f16.f16.f32 "
        "{%0,%1,%2,%3}, {%4,%5,%6,%7}, {%8,%9}, {%0,%1,%2,%3};"
        : "+f"(c[0]), "+f"(c[1]), "+f"(c[2]), "+f"(c[3])
        : "r"(a[0]), "r"(a[1]), "r"(a[2]), "r"(a[3]), "r"(b[0]), "r"(b[1]));
}
__device__ __forceinline__ void red_v2(float* p, float x, float y) {
    asm volatile("red.global.add.v2.f32 [%0], {%1, %2};"
                 :: "l"(p), "f"(x), "f"(y) : "memory");
}

__global__ void __launch_bounds__(THREADS, 2)
expert_scatter_f16(const float* __restrict__ Y,
                   const int*   __restrict__ Ind,
                   float*       __restrict__ out) {
    const int b  = blockIdx.z;
    const int h  = blockIdx.y;
    const int k0 = blockIdx.x * TM;

    extern __shared__ char sm[];
    const uint32_t As_a = smem_u32(sm);
    const uint32_t Bs_a[2] = { As_a + AS_BYTES, As_a + AS_BYTES + BS_BYTES };
    __shared__ int sInd[TM];

    const int tid  = threadIdx.x;
    const int warp = tid >> 5;
    const int lane = tid & 31;
    const int g    = lane >> 2;
    const int tig  = lane & 3;
    const int wm   = warp >> 2;   // 0..1 : 64-row band
    const int wn   = warp & 3;    // 0..3 : 32-col band

    const __half* Wsrc = g_Wh + (size_t)h * DD * NN;

    // ---- Issue cp.async for B chunk 0 first (longest latency) ----
    #pragma unroll
    for (int i = 0; i < 8; i++) {
        const int flat = i * THREADS + tid;
        const int k = flat >> 4;
        const int c = flat & 15;
        cp16(Bs_a[0] + k * 256 + ((c ^ (k & 7)) << 4), Wsrc + (size_t)k * NN + c * 8);
    }
    CP_COMMIT();

    // ---- Stage A: Y[128m x 128k] f32 -> fp16 [m][k], 16B chunks, c ^= m&7 ----
    const float* Yp = Y + ((size_t)(b * HH + h) * KDIM + k0) * DD;
    #pragma unroll
    for (int i = 0; i < 8; i++) {
        const int flat = i * THREADS + tid;
        const int m = flat >> 4;
        const int c = flat & 15;
        const float4 v0 = *(const float4*)(Yp + (size_t)m * DD + c * 8);
        const float4 v1 = *(const float4*)(Yp + (size_t)m * DD + c * 8 + 4);
        uint4 w = { pack_h2(v0.x, v0.y), pack_h2(v0.z, v0.w),
                    pack_h2(v1.x, v1.y), pack_h2(v1.z, v1.w) };
        asm volatile("st.shared.v4.b32 [%0], {%1,%2,%3,%4};"
                     :: "r"(As_a + m * 256 + ((c ^ (m & 7)) << 4)),
                        "r"(w.x), "r"(w.y), "r"(w.z), "r"(w.w) : "memory");
    }
    if (tid < TM) sInd[tid] = Ind[(size_t)(b * HH + h) * KDIM + k0 + tid];

    CP_WAIT0();
    __syncthreads();

    float* outb = out + (size_t)b * TT * NN;

    // per-warp scatter rows
    int t0s[4], t1s[4];
    #pragma unroll
    for (int im = 0; im < 4; im++) {
        const int mrow = wm * 64 + im * 16;
        t0s[im] = sInd[mrow + g];
        t1s[im] = sInd[mrow + g + 8];
    }

    const int a_ml_base = wm * 64 + ((lane >> 3) & 1) * 8 + (lane & 7);
    const int a_chi     = lane >> 4;
    const int b_kl_base = ((lane >> 3) & 1) * 8 + (lane & 7);

    #pragma unroll 1
    for (int nc = 0; nc < NCHUNK; nc++) {
        const int buf = nc & 1;
        const bool has_next = (nc + 1 < NCHUNK);

        // ---- Issue cp.async for next B chunk into other buffer ----
        if (has_next) {
            const __half* Wn = Wsrc + (size_t)(nc + 1) * TN;
            #pragma unroll
            for (int i = 0; i < 8; i++) {
                const int flat = i * THREADS + tid;
                const int k = flat >> 4;
                const int c = flat & 15;
                cp16(Bs_a[buf ^ 1] + k * 256 + ((c ^ (k & 7)) << 4),
                     Wn + (size_t)k * NN + c * 8);
            }
            CP_COMMIT();
        }

        // ---- Compute: warp tile 64m x 32n = 4(im) x 4(in) x 8(kt) ----
        float acc[4][4][4];
        #pragma unroll
        for (int im = 0; im < 4; im++)
            #pragma unroll
            for (int in = 0; in < 4; in++)
                #pragma unroll
                for (int c = 0; c < 4; c++) acc[im][in][c] = 0.f;

        #pragma unroll
        for (int kt = 0; kt < 8; kt++) {
            uint32_t a[4][4], bfr[2][4];
            #pragma unroll
            for (int im = 0; im < 4; im++) {
                const int ml = a_ml_base + im * 16;
                const int c  = kt * 2 + a_chi;
                ldsm_x4(a[im], As_a + ml * 256 + ((c ^ (ml & 7)) << 4));
            }
            #pragma unroll
            for (int inp = 0; inp < 2; inp++) {
                const int kl = kt * 16 + b_kl_base;
                const int c  = wn * 4 + inp * 2 + (lane >> 4);
                ldsm_x4_t(bfr[inp], Bs_a[buf] + kl * 256 + ((c ^ (kl & 7)) << 4));
            }
            #pragma unroll
            for (int in = 0; in < 4; in++) {
                const uint32_t bb[2] = { bfr[in >> 1][(in & 1) * 2],
                                         bfr[in >> 1][(in & 1) * 2 + 1] };
                #pragma unroll
                for (int im = 0; im < 4; im++)
                    mma_f16(acc[im][in], a[im], bb);
            }
        }

        // ---- Epilogue: vectorized scatter-add ----
        const int colb = nc * TN + wn * 32 + tig * 2;
        #pragma unroll
        for (int im = 0; im < 4; im++) {
            float* r0 = outb + (size_t)t0s[im] * NN + colb;
            float* r1 = outb + (size_t)t1s[im] * NN + colb;
            #pragma unroll
            for (int in = 0; in < 4; in++) {
                red_v2(r0 + in * 8, acc[im][in][0], acc[im][in][1]);
                red_v2(r1 + in * 8, acc[im][in][2], acc[im][in][3]);
            }
        }

        if (has_next) {
            CP_WAIT0();
            __syncthreads();
        }
    }
}

extern "C" void kernel_launch(void* const* d_in, const int* in_sizes, int n_in,
                              void* d_out, int out_size) {
    const float* Y   = (const float*)d_in[0];
    const int*   Ind = (const int*)d_in[1];
    const float* W   = (const float*)d_in[n_in - 1];
    float* out = (float*)d_out;

    void* wh_p = nullptr;
    cudaGetSymbolAddress(&wh_p, g_Wh);

    const int n4 = (BB * TT * NN) / 4;
    zero_out_kernel<<<(n4 + 511) / 512, 512>>>((float4*)out, n4);

    const int nw8 = (HH * DD * NN) / 8;
    convert_w_kernel<<<(nw8 + 511) / 512, 512>>>(W, (__half*)wh_p, nw8);

    cudaFuncSetAttribute(expert_scatter_f16,
                         cudaFuncAttributeMaxDynamicSharedMemorySize, SMEM_BYTES);
    dim3 grid(KDIM / TM, HH, BB);   // 8 x 16 x 8 = 1024 CTAs
    expert_scatter_f16<<<grid, THREADS, SMEM_BYTES>>>(Y, Ind, out);
}